// round 16
// baseline (speedup 1.0000x reference)
#include <cuda_runtime.h>
#include <cuda_fp16.h>
#include <float.h>
#include <math.h>

#define DMODEL 512
#define NHEAD  8
#define HDIM   64
#define BATCH  4
#define SEQ    2048

// 0.125 * log2(e): folded into Q projection so S from MMA is already exp2-ready
#define QSCALE 0.18033688011112042f

// Scratch (allocation-free rule: __device__ globals)
__device__ __align__(256) __half g_qh[BATCH * NHEAD * SEQ * HDIM];
__device__ __align__(256) __half g_kh[BATCH * NHEAD * SEQ * HDIM];
__device__ __align__(256) __half g_vh[BATCH * DMODEL * SEQ];
__device__ __align__(256) float  g_x [BATCH * DMODEL * SEQ];
__device__ unsigned g_flagbits[BATCH * SEQ];   // bit mt: tile fully unmasked

// ---------------------------------------------------------------------------
__device__ __forceinline__ void mma16816(float* c, const unsigned* a,
                                         unsigned b0, unsigned b1) {
    asm volatile(
        "mma.sync.aligned.m16n8k16.row.col.f32.f16.f16.f32 "
        "{%0,%1,%2,%3}, {%4,%5,%6,%7}, {%8,%9}, {%0,%1,%2,%3};"
        : "+f"(c[0]), "+f"(c[1]), "+f"(c[2]), "+f"(c[3])
        : "r"(a[0]), "r"(a[1]), "r"(a[2]), "r"(a[3]), "r"(b0), "r"(b1));
}

__device__ __forceinline__ void ldsm_x4(unsigned* r, unsigned addr) {
    asm volatile("ldmatrix.sync.aligned.m8n8.x4.shared.b16 {%0,%1,%2,%3}, [%4];"
        : "=r"(r[0]), "=r"(r[1]), "=r"(r[2]), "=r"(r[3]) : "r"(addr));
}

__device__ __forceinline__ unsigned pack_h2(float lo, float hi) {
    unsigned r;
    asm("cvt.rn.f16x2.f32 %0, %1, %2;" : "=r"(r) : "f"(hi), "f"(lo));
    return r;
}
__device__ __forceinline__ unsigned ex2_h2(unsigned x) {
    unsigned r;
    asm("ex2.approx.f16x2 %0, %1;" : "=r"(r) : "r"(x));
    return r;
}

__device__ __forceinline__ void cp16(unsigned dst, const void* src) {
    asm volatile("cp.async.ca.shared.global [%0], [%1], 16;" :: "r"(dst), "l"(src));
}
__device__ __forceinline__ void cp_commit() {
    asm volatile("cp.async.commit_group;");
}
template <int N>
__device__ __forceinline__ void cp_wait() {
    asm volatile("cp.async.wait_group %0;" :: "n"(N));
}

// ---------------------------------------------------------------------------
// fp16 tensor-core projection GEMM (round-8/13 scalar-LDS version):
// Y = oscale * (W X + bias). CTA tile 128x128, k-chunk 32, 8 warps 4x2.
// SPLIT=1: W,X split hi+lo fp16, 3 MMAs. TRANS=1: write [h][n][d] layout.
// ---------------------------------------------------------------------------
#define PS 40
#define TS 130

template <int SPLIT, int TRANS, typename YT>
__device__ __forceinline__ void proj16_tile(const float* __restrict__ X,
                                            const float* __restrict__ W,
                                            const float* __restrict__ bias,
                                            YT* __restrict__ Y, float oscale) {
    __shared__ __align__(16) __half PB[4 * 128 * PS];
    __half* Wh = PB;
    __half* Xh = PB + 128 * PS;
    __half* Wl = PB + 2 * 128 * PS;
    __half* Xl = PB + 3 * 128 * PS;

    const int tid = threadIdx.x;
    const int wid = tid >> 5, lane = tid & 31;
    const int g = lane >> 2, t = lane & 3;
    const int wo = (wid >> 1) * 32;
    const int wn = (wid & 1) * 64;
    const int n0 = blockIdx.x * 128;
    const int o0 = blockIdx.y * 128;

    float acc[2][8][4];
#pragma unroll
    for (int mt = 0; mt < 2; mt++)
#pragma unroll
        for (int nb = 0; nb < 8; nb++)
#pragma unroll
            for (int i = 0; i < 4; i++) acc[mt][nb][i] = 0.f;

    const int lo_o = tid >> 1;
    const int lo_k = (tid & 1) * 16;
    const int lx_n = tid & 127;
    const int lx_k = (tid >> 7) * 16;

    for (int k0 = 0; k0 < DMODEL; k0 += 32) {
        float wv[16], xv[16];
        const float* wp = &W[(size_t)(o0 + lo_o) * DMODEL + k0 + lo_k];
#pragma unroll
        for (int j = 0; j < 4; j++) *(float4*)&wv[4 * j] = *(const float4*)&wp[4 * j];
#pragma unroll
        for (int j = 0; j < 16; j++)
            xv[j] = X[(size_t)(k0 + lx_k + j) * SEQ + n0 + lx_n];

        __syncthreads();

        unsigned uw[8], ux[8];
#pragma unroll
        for (int j = 0; j < 8; j++) {
            __half2 hw = __floats2half2_rn(wv[2 * j], wv[2 * j + 1]);
            __half2 hx = __floats2half2_rn(xv[2 * j], xv[2 * j + 1]);
            uw[j] = *(unsigned*)&hw;
            ux[j] = *(unsigned*)&hx;
        }
        *(uint4*)&Wh[lo_o * PS + lo_k]     = make_uint4(uw[0], uw[1], uw[2], uw[3]);
        *(uint4*)&Wh[lo_o * PS + lo_k + 8] = make_uint4(uw[4], uw[5], uw[6], uw[7]);
        *(uint4*)&Xh[lx_n * PS + lx_k]     = make_uint4(ux[0], ux[1], ux[2], ux[3]);
        *(uint4*)&Xh[lx_n * PS + lx_k + 8] = make_uint4(ux[4], ux[5], ux[6], ux[7]);
        if (SPLIT) {
#pragma unroll
            for (int j = 0; j < 8; j++) {
                __half2 hw = *(__half2*)&uw[j];
                __half2 hx = *(__half2*)&ux[j];
                __half2 lw = __floats2half2_rn(wv[2 * j]     - __low2float(hw),
                                               wv[2 * j + 1] - __high2float(hw));
                __half2 lx = __floats2half2_rn(xv[2 * j]     - __low2float(hx),
                                               xv[2 * j + 1] - __high2float(hx));
                uw[j] = *(unsigned*)&lw;
                ux[j] = *(unsigned*)&lx;
            }
            *(uint4*)&Wl[lo_o * PS + lo_k]     = make_uint4(uw[0], uw[1], uw[2], uw[3]);
            *(uint4*)&Wl[lo_o * PS + lo_k + 8] = make_uint4(uw[4], uw[5], uw[6], uw[7]);
            *(uint4*)&Xl[lx_n * PS + lx_k]     = make_uint4(ux[0], ux[1], ux[2], ux[3]);
            *(uint4*)&Xl[lx_n * PS + lx_k + 8] = make_uint4(ux[4], ux[5], ux[6], ux[7]);
        }
        __syncthreads();

#pragma unroll
        for (int ks = 0; ks < 2; ks++) {
            unsigned a[2][4], al[2][4];
#pragma unroll
            for (int mt = 0; mt < 2; mt++) {
                const int row = wo + mt * 16 + g;
                a[mt][0] = *(const unsigned*)&Wh[row * PS + ks * 16 + 2 * t];
                a[mt][1] = *(const unsigned*)&Wh[(row + 8) * PS + ks * 16 + 2 * t];
                a[mt][2] = *(const unsigned*)&Wh[row * PS + ks * 16 + 2 * t + 8];
                a[mt][3] = *(const unsigned*)&Wh[(row + 8) * PS + ks * 16 + 2 * t + 8];
                if (SPLIT) {
                    al[mt][0] = *(const unsigned*)&Wl[row * PS + ks * 16 + 2 * t];
                    al[mt][1] = *(const unsigned*)&Wl[(row + 8) * PS + ks * 16 + 2 * t];
                    al[mt][2] = *(const unsigned*)&Wl[row * PS + ks * 16 + 2 * t + 8];
                    al[mt][3] = *(const unsigned*)&Wl[(row + 8) * PS + ks * 16 + 2 * t + 8];
                }
            }
#pragma unroll
            for (int nb = 0; nb < 8; nb++) {
                const int col = wn + nb * 8 + g;
                unsigned b0 = *(const unsigned*)&Xh[col * PS + ks * 16 + 2 * t];
                unsigned b1 = *(const unsigned*)&Xh[col * PS + ks * 16 + 2 * t + 8];
#pragma unroll
                for (int mt = 0; mt < 2; mt++) mma16816(acc[mt][nb], a[mt], b0, b1);
                if (SPLIT) {
#pragma unroll
                    for (int mt = 0; mt < 2; mt++) mma16816(acc[mt][nb], al[mt], b0, b1);
                    unsigned bl0 = *(const unsigned*)&Xl[col * PS + ks * 16 + 2 * t];
                    unsigned bl1 = *(const unsigned*)&Xl[col * PS + ks * 16 + 2 * t + 8];
#pragma unroll
                    for (int mt = 0; mt < 2; mt++) mma16816(acc[mt][nb], a[mt], bl0, bl1);
                }
            }
        }
    }

    if (TRANS) {
        __syncthreads();
        __half* Tile = PB;
#pragma unroll
        for (int mt = 0; mt < 2; mt++) {
            const int row = wo + mt * 16 + g;
            const float bv0 = bias[o0 + row];
            const float bv1 = bias[o0 + row + 8];
#pragma unroll
            for (int nb = 0; nb < 8; nb++) {
                const int col = wn + nb * 8 + 2 * t;
                __half2 h0 = __floats2half2_rn((acc[mt][nb][0] + bv0) * oscale,
                                               (acc[mt][nb][1] + bv0) * oscale);
                __half2 h1 = __floats2half2_rn((acc[mt][nb][2] + bv1) * oscale,
                                               (acc[mt][nb][3] + bv1) * oscale);
                *(__half2*)&Tile[row * TS + col]       = h0;
                *(__half2*)&Tile[(row + 8) * TS + col] = h1;
            }
        }
        __syncthreads();
        const unsigned short* TU = (const unsigned short*)Tile;
#pragma unroll
        for (int r = 0; r < 4; r++) {
            const int p = r * 256 + tid;
            const int hh = p >> 7, n = p & 127;
            unsigned u[8];
#pragma unroll
            for (int j = 0; j < 8; j++) {
                unsigned short a0 = TU[((2 * j) * 8 + hh) * TS + n];
                unsigned short a1 = TU[((2 * j + 1) * 8 + hh) * TS + n];
                u[j] = a0 | ((unsigned)a1 << 16);
            }
            __half* dst = (__half*)Y + ((size_t)hh * SEQ + n0 + n) * HDIM + (o0 >> 3);
            *(uint4*)dst       = make_uint4(u[0], u[1], u[2], u[3]);
            *(uint4*)(dst + 8) = make_uint4(u[4], u[5], u[6], u[7]);
        }
    } else {
#pragma unroll
        for (int mt = 0; mt < 2; mt++) {
            const int row = o0 + wo + mt * 16 + g;
            const float bv0 = bias[row];
            const float bv1 = bias[row + 8];
#pragma unroll
            for (int nb = 0; nb < 8; nb++) {
                const int col = n0 + wn + nb * 8 + 2 * t;
                float c0 = acc[mt][nb][0] + bv0, c1 = acc[mt][nb][1] + bv0;
                float c2 = acc[mt][nb][2] + bv1, c3 = acc[mt][nb][3] + bv1;
                if constexpr (sizeof(YT) == 2) {
                    __half2 h0 = __floats2half2_rn(c0, c1);
                    __half2 h1 = __floats2half2_rn(c2, c3);
                    *(unsigned*)&Y[(size_t)row * SEQ + col]       = *(unsigned*)&h0;
                    *(unsigned*)&Y[(size_t)(row + 8) * SEQ + col] = *(unsigned*)&h1;
                } else {
                    *(float2*)&Y[(size_t)row * SEQ + col]       = make_float2(c0, c1);
                    *(float2*)&Y[(size_t)(row + 8) * SEQ + col] = make_float2(c2, c3);
                }
            }
        }
    }
}

__global__ void __launch_bounds__(256, 2)
proj_qkv_kernel(const float* __restrict__ q, const float* __restrict__ k,
                const float* __restrict__ v,
                const float* __restrict__ Wq, const float* __restrict__ bq,
                const float* __restrict__ Wk, const float* __restrict__ bk,
                const float* __restrict__ Wv, const float* __restrict__ bv) {
    const int b = blockIdx.z & 3;
    const int which = blockIdx.z >> 2;   // 0:q 1:k 2:v
    const size_t off = (size_t)b * DMODEL * SEQ;
    if (which == 0)
        proj16_tile<0, 1, __half>(q + off, Wq, bq,
                                  g_qh + (size_t)b * NHEAD * SEQ * HDIM, QSCALE);
    else if (which == 1)
        proj16_tile<0, 1, __half>(k + off, Wk, bk,
                                  g_kh + (size_t)b * NHEAD * SEQ * HDIM, 1.f);
    else
        proj16_tile<0, 0, __half>(v + off, Wv, bv, g_vh + off, 1.f);
}

__global__ void __launch_bounds__(256, 2)
proj_out_kernel(const float* __restrict__ Wm, const float* __restrict__ bm,
                float* __restrict__ out) {
    const int b = blockIdx.z;
    const size_t off = (size_t)b * DMODEL * SEQ;
    proj16_tile<1, 0, float>(g_x + off, Wm, bm, out + off, 1.f);
}

// ---------------------------------------------------------------------------
__global__ void __launch_bounds__(256)
flags_kernel(const int* __restrict__ M) {
    const int row = blockIdx.x * 8 + (threadIdx.x >> 5);
    const int mt  = threadIdx.x & 31;
    const int4* p = (const int4*)(M + (size_t)row * SEQ + mt * 64);
    int ok = 1;
#pragma unroll
    for (int i = 0; i < 16; i++) {
        int4 v = p[i];
        ok &= (v.x == 1) & (v.y == 1) & (v.z == 1) & (v.w == 1);
    }
    unsigned bits = __ballot_sync(0xffffffffu, ok);
    if (mt == 0) g_flagbits[row] = bits;
}

// ---------------------------------------------------------------------------
// Flash attention: fp16 HMMA, ldmatrix frags, 4-stage cp.async K/V buffers,
// tiles processed in PAIRS: one cp_wait + one __syncthreads per pair (16
// rendezvous instead of 32). Refill of pair pt+1 happens after the barrier
// at iter pt (its stages were consumed at iter pt-1 — provably done).
// smem: Qs[128*AS] | Ks[4][64*AS] | Vs[4][72*AS] (V rows 64..71: ones/zeros)
// ---------------------------------------------------------------------------
#define AS 72
#define Q_OFF 0
#define K_OFF (128 * AS)
#define KSTG  (64 * AS)
#define V_OFF (K_OFF + 4 * KSTG)
#define VSTG  (72 * AS)
#define SH_HALVES (V_OFF + 4 * VSTG)

__device__ __forceinline__ void attn_load_kv(unsigned sb, const __half* Kg,
                                             const __half* Vg, int h, int st,
                                             int m0, int tid) {
#pragma unroll
    for (int r = 0; r < 2; r++) {
        const int idx = tid + 256 * r;
        const int m = idx >> 3, c = idx & 7;
        cp16(sb + (K_OFF + st * KSTG + m * AS + c * 8) * 2,
             Kg + (size_t)(m0 + m) * HDIM + c * 8);
    }
#pragma unroll
    for (int r = 0; r < 2; r++) {
        const int idx = tid + 256 * r;
        const int d = idx >> 3, c = idx & 7;
        cp16(sb + (V_OFF + st * VSTG + d * AS + c * 8) * 2,
             Vg + (size_t)(d * 8 + h) * SEQ + m0 + c * 8);
    }
}

__global__ void __launch_bounds__(256, 2)
attn_kernel(const int* __restrict__ Mmask) {
    extern __shared__ __align__(16) __half sh[];

    const int tid  = threadIdx.x;
    const int wid  = tid >> 5;
    const int lane = tid & 31;
    const int g = lane >> 2;
    const int t = lane & 3;
    const int n0 = blockIdx.x * 128;
    const int b = blockIdx.y >> 3;
    const int h = blockIdx.y & 7;
    const int bh = b * NHEAD + h;

    const __half* Qg = g_qh + (size_t)bh * SEQ * HDIM;
    const __half* Kg = g_kh + (size_t)bh * SEQ * HDIM;
    const __half* Vg = g_vh + (size_t)b * DMODEL * SEQ;
    const unsigned sb = (unsigned)__cvta_generic_to_shared(sh);

    // ldmatrix per-lane base offset within a K/V stage
    const unsigned kbl = (unsigned)((lane & 7) * AS +
                                    ((lane >> 3) & 1) * 8 + (lane >> 4) * 16) * 2;

    // prologue: group0 = Q + pair0 (tiles 0,1); group1 = pair1 (tiles 2,3)
#pragma unroll
    for (int r = 0; r < 4; r++) {
        const int idx = tid + 256 * r;
        const int n = idx >> 3, c = idx & 7;
        cp16(sb + (Q_OFF + n * AS + c * 8) * 2,
             Qg + (size_t)(n0 + n) * HDIM + c * 8);
    }
    attn_load_kv(sb, Kg, Vg, h, 0, 0, tid);
    attn_load_kv(sb, Kg, Vg, h, 1, 64, tid);
    cp_commit();
    attn_load_kv(sb, Kg, Vg, h, 2, 128, tid);
    attn_load_kv(sb, Kg, Vg, h, 3, 192, tid);
    cp_commit();

    // ones/zeros rows 64..71 of the 4 V stages (row 64 = 1.0 -> l = P @ ones)
    {
        const __half one = __float2half(1.0f);
        const __half zer = __float2half(0.0f);
        for (int idx = tid; idx < 4 * 8 * 64; idx += 256) {
            const int st = idx >> 9;
            const int r  = (idx >> 6) & 7;
            const int c  = idx & 63;
            sh[V_OFF + st * VSTG + (64 + r) * AS + c] = (r == 0) ? one : zer;
        }
    }

    cp_wait<1>();          // group0 (Q + pair0) resident
    __syncthreads();

    unsigned qA[4][4];
    const int row_s = 16 * wid + g;
#pragma unroll
    for (int ks = 0; ks < 4; ks++) {
        qA[ks][0] = *(const unsigned*)&sh[Q_OFF + row_s * AS + 16 * ks + 2 * t];
        qA[ks][1] = *(const unsigned*)&sh[Q_OFF + (row_s + 8) * AS + 16 * ks + 2 * t];
        qA[ks][2] = *(const unsigned*)&sh[Q_OFF + row_s * AS + 16 * ks + 2 * t + 8];
        qA[ks][3] = *(const unsigned*)&sh[Q_OFF + (row_s + 8) * AS + 16 * ks + 2 * t + 8];
    }

    const int row0 = n0 + 16 * wid + g;
    const unsigned fb0 = g_flagbits[(size_t)b * SEQ + row0];
    const unsigned fb1 = g_flagbits[(size_t)b * SEQ + row0 + 8];

    float o[8][4], accl[4];
#pragma unroll
    for (int db = 0; db < 8; db++)
#pragma unroll
        for (int i = 0; i < 4; i++) o[db][i] = 0.f;
#pragma unroll
    for (int i = 0; i < 4; i++) accl[i] = 0.f;

    for (int pt = 0; pt < 16; pt++) {
        if (pt) {
            cp_wait<0>();       // pair pt's loads (committed at iter pt-1) done
            __syncthreads();    // all warps finished pair pt-1 -> stages free
            if (pt + 1 < 16) {  // refill pair pt+1 (stages consumed at pt-1)
                attn_load_kv(sb, Kg, Vg, h, (2 * pt + 2) & 3, (2 * pt + 2) * 64, tid);
                attn_load_kv(sb, Kg, Vg, h, (2 * pt + 3) & 3, (2 * pt + 3) * 64, tid);
                cp_commit();
            }
        }

#pragma unroll
        for (int half = 0; half < 2; half++) {
            const int mt = 2 * pt + half;
            const int m0 = mt * 64;
            const int s = mt & 3;
            const unsigned kaddr = sb + (unsigned)(K_OFF + s * KSTG) * 2 + kbl;
            const unsigned vaddr = sb + (unsigned)(V_OFF + s * VSTG) * 2 + kbl;

            // ---- S = Q K^T (already exp2-scaled via Q prescale) ----
            float s_[8][4];
#pragma unroll
            for (int nb = 0; nb < 8; nb++) {
#pragma unroll
                for (int i = 0; i < 4; i++) s_[nb][i] = 0.f;
                unsigned kf[8];
                const unsigned ka = kaddr + (unsigned)(8 * nb * AS) * 2;
                ldsm_x4(kf, ka);
                ldsm_x4(kf + 4, ka + 64);
                mma16816(s_[nb], qA[0], kf[0], kf[1]);
                mma16816(s_[nb], qA[1], kf[2], kf[3]);
                mma16816(s_[nb], qA[2], kf[4], kf[5]);
                mma16816(s_[nb], qA[3], kf[6], kf[7]);
            }

            // ---- mask (rare path) ----
            if (!(((fb0 >> mt) & 1u) & ((fb1 >> mt) & 1u))) {
#pragma unroll
                for (int nb = 0; nb < 8; nb++) {
                    int2 mv0 = *(const int2*)&Mmask[((size_t)b * SEQ + row0) * SEQ + m0 + 8 * nb + 2 * t];
                    int2 mv1 = *(const int2*)&Mmask[((size_t)b * SEQ + row0 + 8) * SEQ + m0 + 8 * nb + 2 * t];
                    if (mv0.x != 1) s_[nb][0] = -FLT_MAX;
                    if (mv0.y != 1) s_[nb][1] = -FLT_MAX;
                    if (mv1.x != 1) s_[nb][2] = -FLT_MAX;
                    if (mv1.y != 1) s_[nb][3] = -FLT_MAX;
                }
            }

            // ---- p = 2^s, packed fp16 ----
            unsigned pa0[8], pa1[8];
#pragma unroll
            for (int nb = 0; nb < 8; nb++) {
                pa0[nb] = ex2_h2(pack_h2(s_[nb][0], s_[nb][1]));
                pa1[nb] = ex2_h2(pack_h2(s_[nb][2], s_[nb][3]));
            }

            // ---- O += P V ----
#pragma unroll
            for (int db = 0; db < 8; db++) {
                unsigned vf[8];
                const unsigned va = vaddr + (unsigned)(8 * db * AS) * 2;
                ldsm_x4(vf, va);
                ldsm_x4(vf + 4, va + 64);
                { unsigned a[4] = {pa0[0], pa1[0], pa0[1], pa1[1]}; mma16816(o[db], a, vf[0], vf[1]); }
                { unsigned a[4] = {pa0[2], pa1[2], pa0[3], pa1[3]}; mma16816(o[db], a, vf[2], vf[3]); }
                { unsigned a[4] = {pa0[4], pa1[4], pa0[5], pa1[5]}; mma16816(o[db], a, vf[4], vf[5]); }
                { unsigned a[4] = {pa0[6], pa1[6], pa0[7], pa1[7]}; mma16816(o[db], a, vf[6], vf[7]); }
            }
            // ---- l += P @ ones (V rows 64..71) ----
            {
                unsigned lf[8];
                const unsigned la = vaddr + (unsigned)(64 * AS) * 2;
                ldsm_x4(lf, la);
                ldsm_x4(lf + 4, la + 64);
                { unsigned a[4] = {pa0[0], pa1[0], pa0[1], pa1[1]}; mma16816(accl, a, lf[0], lf[1]); }
                { unsigned a[4] = {pa0[2], pa1[2], pa0[3], pa1[3]}; mma16816(accl, a, lf[2], lf[3]); }
                { unsigned a[4] = {pa0[4], pa1[4], pa0[5], pa1[5]}; mma16816(accl, a, lf[4], lf[5]); }
                { unsigned a[4] = {pa0[6], pa1[6], pa0[7], pa1[7]}; mma16816(accl, a, lf[6], lf[7]); }
            }
        }
    }

    // ---- l lives in column 0 of the extra block (t==0 lanes) ----
    const float l0 = __shfl_sync(0xffffffffu, accl[0], lane & 28);
    const float l1 = __shfl_sync(0xffffffffu, accl[2], lane & 28);
    const float inv0 = 1.f / l0;
    const float inv1 = 1.f / l1;

    float* Xb = g_x + (size_t)b * DMODEL * SEQ;
#pragma unroll
    for (int db = 0; db < 8; db++) {
        const int d0 = 8 * db + 2 * t;
        Xb[(size_t)(d0 * 8 + h) * SEQ + row0]           = o[db][0] * inv0;
        Xb[(size_t)((d0 + 1) * 8 + h) * SEQ + row0]     = o[db][1] * inv0;
        Xb[(size_t)(d0 * 8 + h) * SEQ + row0 + 8]       = o[db][2] * inv1;
        Xb[(size_t)((d0 + 1) * 8 + h) * SEQ + row0 + 8] = o[db][3] * inv1;
    }
}

// ---------------------------------------------------------------------------
extern "C" void kernel_launch(void* const* d_in, const int* in_sizes, int n_in,
                              void* d_out, int out_size) {
    const float* q  = (const float*)d_in[0];
    const float* k  = (const float*)d_in[1];
    const float* v  = (const float*)d_in[2];
    const int*   Mm = (const int*)  d_in[3];
    const float* Wq = (const float*)d_in[4];
    const float* bq = (const float*)d_in[5];
    const float* Wk = (const float*)d_in[6];
    const float* bk = (const float*)d_in[7];
    const float* Wv = (const float*)d_in[8];
    const float* bv = (const float*)d_in[9];
    const float* Wm = (const float*)d_in[10];
    const float* bm = (const float*)d_in[11];
    float* out = (float*)d_out;

    flags_kernel<<<BATCH * SEQ / 8, 256>>>(Mm);

    dim3 gqkv(SEQ / 128, DMODEL / 128, 3 * BATCH);
    proj_qkv_kernel<<<gqkv, 256>>>(q, k, v, Wq, bq, Wk, bk, Wv, bv);

    const int smem_attn = SH_HALVES * 2;
    cudaFuncSetAttribute(attn_kernel, cudaFuncAttributeMaxDynamicSharedMemorySize, smem_attn);
    dim3 gattn(SEQ / 128, BATCH * NHEAD);
    attn_kernel<<<gattn, 256, smem_attn>>>(Mm);

    dim3 gout(SEQ / 128, DMODEL / 128, BATCH);
    proj_out_kernel<<<gout, 256>>>(Wm, bm, out);
}

// round 17
// speedup vs baseline: 1.0580x; 1.0580x over previous
#include <cuda_runtime.h>
#include <cuda_fp16.h>
#include <float.h>
#include <math.h>

#define DMODEL 512
#define NHEAD  8
#define HDIM   64
#define BATCH  4
#define SEQ    2048

// 0.125 * log2(e): folded into Q projection so S from MMA is already exp2-ready
#define QSCALE 0.18033688011112042f

// Scratch (allocation-free rule: __device__ globals)
__device__ __align__(256) __half g_qh[BATCH * NHEAD * SEQ * HDIM];
__device__ __align__(256) __half g_kh[BATCH * NHEAD * SEQ * HDIM];
__device__ __align__(256) __half g_vh[BATCH * DMODEL * SEQ];
__device__ __align__(256) float  g_x [BATCH * DMODEL * SEQ];
__device__ unsigned g_flagbits[BATCH * SEQ];   // bit mt: tile fully unmasked

// ---------------------------------------------------------------------------
__device__ __forceinline__ void mma16816(float* c, const unsigned* a,
                                         unsigned b0, unsigned b1) {
    asm volatile(
        "mma.sync.aligned.m16n8k16.row.col.f32.f16.f16.f32 "
        "{%0,%1,%2,%3}, {%4,%5,%6,%7}, {%8,%9}, {%0,%1,%2,%3};"
        : "+f"(c[0]), "+f"(c[1]), "+f"(c[2]), "+f"(c[3])
        : "r"(a[0]), "r"(a[1]), "r"(a[2]), "r"(a[3]), "r"(b0), "r"(b1));
}

__device__ __forceinline__ void ldsm_x4(unsigned* r, unsigned addr) {
    asm volatile("ldmatrix.sync.aligned.m8n8.x4.shared.b16 {%0,%1,%2,%3}, [%4];"
        : "=r"(r[0]), "=r"(r[1]), "=r"(r[2]), "=r"(r[3]) : "r"(addr));
}

__device__ __forceinline__ unsigned pack_h2(float lo, float hi) {
    unsigned r;
    asm("cvt.rn.f16x2.f32 %0, %1, %2;" : "=r"(r) : "f"(hi), "f"(lo));
    return r;
}
__device__ __forceinline__ unsigned ex2_h2(unsigned x) {
    unsigned r;
    asm("ex2.approx.f16x2 %0, %1;" : "=r"(r) : "r"(x));
    return r;
}

__device__ __forceinline__ void cp16(unsigned dst, const void* src) {
    asm volatile("cp.async.ca.shared.global [%0], [%1], 16;" :: "r"(dst), "l"(src));
}
__device__ __forceinline__ void cp_commit() {
    asm volatile("cp.async.commit_group;");
}
template <int N>
__device__ __forceinline__ void cp_wait() {
    asm volatile("cp.async.wait_group %0;" :: "n"(N));
}

// ---------------------------------------------------------------------------
// fp16 tensor-core projection GEMM: Y = oscale * (W X + bias)
// CTA tile 128x128, k-chunk 32, 8 warps 4x2.
// SPLIT=1: W split hi+lo fp16, 2 MMA passes (WhXh + WlXh); X hi only.
// TRANS=1: write [h][n][d] layout.
// ---------------------------------------------------------------------------
#define PS 40
#define TS 130

template <int SPLIT, int TRANS, typename YT>
__device__ __forceinline__ void proj16_tile(const float* __restrict__ X,
                                            const float* __restrict__ W,
                                            const float* __restrict__ bias,
                                            YT* __restrict__ Y, float oscale) {
    __shared__ __align__(16) __half PB[4 * 128 * PS];
    __half* Wh = PB;
    __half* Xh = PB + 128 * PS;
    __half* Wl = PB + 2 * 128 * PS;   // used iff SPLIT

    const int tid = threadIdx.x;
    const int wid = tid >> 5, lane = tid & 31;
    const int g = lane >> 2, t = lane & 3;
    const int wo = (wid >> 1) * 32;
    const int wn = (wid & 1) * 64;
    const int n0 = blockIdx.x * 128;
    const int o0 = blockIdx.y * 128;

    float acc[2][8][4];
#pragma unroll
    for (int mt = 0; mt < 2; mt++)
#pragma unroll
        for (int nb = 0; nb < 8; nb++)
#pragma unroll
            for (int i = 0; i < 4; i++) acc[mt][nb][i] = 0.f;

    const int lo_o = tid >> 1;
    const int lo_k = (tid & 1) * 16;
    const int lx_n = tid & 127;
    const int lx_k = (tid >> 7) * 16;

    for (int k0 = 0; k0 < DMODEL; k0 += 32) {
        float wv[16], xv[16];
        const float* wp = &W[(size_t)(o0 + lo_o) * DMODEL + k0 + lo_k];
#pragma unroll
        for (int j = 0; j < 4; j++) *(float4*)&wv[4 * j] = *(const float4*)&wp[4 * j];
#pragma unroll
        for (int j = 0; j < 16; j++)
            xv[j] = X[(size_t)(k0 + lx_k + j) * SEQ + n0 + lx_n];

        __syncthreads();

        unsigned uw[8], ux[8];
#pragma unroll
        for (int j = 0; j < 8; j++) {
            __half2 hw = __floats2half2_rn(wv[2 * j], wv[2 * j + 1]);
            __half2 hx = __floats2half2_rn(xv[2 * j], xv[2 * j + 1]);
            uw[j] = *(unsigned*)&hw;
            ux[j] = *(unsigned*)&hx;
        }
        *(uint4*)&Wh[lo_o * PS + lo_k]     = make_uint4(uw[0], uw[1], uw[2], uw[3]);
        *(uint4*)&Wh[lo_o * PS + lo_k + 8] = make_uint4(uw[4], uw[5], uw[6], uw[7]);
        *(uint4*)&Xh[lx_n * PS + lx_k]     = make_uint4(ux[0], ux[1], ux[2], ux[3]);
        *(uint4*)&Xh[lx_n * PS + lx_k + 8] = make_uint4(ux[4], ux[5], ux[6], ux[7]);
        if (SPLIT) {
#pragma unroll
            for (int j = 0; j < 8; j++) {
                __half2 hw = *(__half2*)&uw[j];
                __half2 lw = __floats2half2_rn(wv[2 * j]     - __low2float(hw),
                                               wv[2 * j + 1] - __high2float(hw));
                uw[j] = *(unsigned*)&lw;
            }
            *(uint4*)&Wl[lo_o * PS + lo_k]     = make_uint4(uw[0], uw[1], uw[2], uw[3]);
            *(uint4*)&Wl[lo_o * PS + lo_k + 8] = make_uint4(uw[4], uw[5], uw[6], uw[7]);
        }
        __syncthreads();

#pragma unroll
        for (int ks = 0; ks < 2; ks++) {
            unsigned a[2][4], al[2][4];
#pragma unroll
            for (int mt = 0; mt < 2; mt++) {
                const int row = wo + mt * 16 + g;
                a[mt][0] = *(const unsigned*)&Wh[row * PS + ks * 16 + 2 * t];
                a[mt][1] = *(const unsigned*)&Wh[(row + 8) * PS + ks * 16 + 2 * t];
                a[mt][2] = *(const unsigned*)&Wh[row * PS + ks * 16 + 2 * t + 8];
                a[mt][3] = *(const unsigned*)&Wh[(row + 8) * PS + ks * 16 + 2 * t + 8];
                if (SPLIT) {
                    al[mt][0] = *(const unsigned*)&Wl[row * PS + ks * 16 + 2 * t];
                    al[mt][1] = *(const unsigned*)&Wl[(row + 8) * PS + ks * 16 + 2 * t];
                    al[mt][2] = *(const unsigned*)&Wl[row * PS + ks * 16 + 2 * t + 8];
                    al[mt][3] = *(const unsigned*)&Wl[(row + 8) * PS + ks * 16 + 2 * t + 8];
                }
            }
#pragma unroll
            for (int nb = 0; nb < 8; nb++) {
                const int col = wn + nb * 8 + g;
                unsigned b0 = *(const unsigned*)&Xh[col * PS + ks * 16 + 2 * t];
                unsigned b1 = *(const unsigned*)&Xh[col * PS + ks * 16 + 2 * t + 8];
#pragma unroll
                for (int mt = 0; mt < 2; mt++) mma16816(acc[mt][nb], a[mt], b0, b1);
                if (SPLIT) {
#pragma unroll
                    for (int mt = 0; mt < 2; mt++) mma16816(acc[mt][nb], al[mt], b0, b1);
                }
            }
        }
    }

    if (TRANS) {
        __syncthreads();
        __half* Tile = PB;
#pragma unroll
        for (int mt = 0; mt < 2; mt++) {
            const int row = wo + mt * 16 + g;
            const float bv0 = bias[o0 + row];
            const float bv1 = bias[o0 + row + 8];
#pragma unroll
            for (int nb = 0; nb < 8; nb++) {
                const int col = wn + nb * 8 + 2 * t;
                __half2 h0 = __floats2half2_rn((acc[mt][nb][0] + bv0) * oscale,
                                               (acc[mt][nb][1] + bv0) * oscale);
                __half2 h1 = __floats2half2_rn((acc[mt][nb][2] + bv1) * oscale,
                                               (acc[mt][nb][3] + bv1) * oscale);
                *(__half2*)&Tile[row * TS + col]       = h0;
                *(__half2*)&Tile[(row + 8) * TS + col] = h1;
            }
        }
        __syncthreads();
        const unsigned short* TU = (const unsigned short*)Tile;
#pragma unroll
        for (int r = 0; r < 4; r++) {
            const int p = r * 256 + tid;
            const int hh = p >> 7, n = p & 127;
            unsigned u[8];
#pragma unroll
            for (int j = 0; j < 8; j++) {
                unsigned short a0 = TU[((2 * j) * 8 + hh) * TS + n];
                unsigned short a1 = TU[((2 * j + 1) * 8 + hh) * TS + n];
                u[j] = a0 | ((unsigned)a1 << 16);
            }
            __half* dst = (__half*)Y + ((size_t)hh * SEQ + n0 + n) * HDIM + (o0 >> 3);
            *(uint4*)dst       = make_uint4(u[0], u[1], u[2], u[3]);
            *(uint4*)(dst + 8) = make_uint4(u[4], u[5], u[6], u[7]);
        }
    } else {
#pragma unroll
        for (int mt = 0; mt < 2; mt++) {
            const int row = o0 + wo + mt * 16 + g;
            const float bv0 = bias[row];
            const float bv1 = bias[row + 8];
#pragma unroll
            for (int nb = 0; nb < 8; nb++) {
                const int col = n0 + wn + nb * 8 + 2 * t;
                float c0 = acc[mt][nb][0] + bv0, c1 = acc[mt][nb][1] + bv0;
                float c2 = acc[mt][nb][2] + bv1, c3 = acc[mt][nb][3] + bv1;
                if constexpr (sizeof(YT) == 2) {
                    __half2 h0 = __floats2half2_rn(c0, c1);
                    __half2 h1 = __floats2half2_rn(c2, c3);
                    *(unsigned*)&Y[(size_t)row * SEQ + col]       = *(unsigned*)&h0;
                    *(unsigned*)&Y[(size_t)(row + 8) * SEQ + col] = *(unsigned*)&h1;
                } else {
                    *(float2*)&Y[(size_t)row * SEQ + col]       = make_float2(c0, c1);
                    *(float2*)&Y[(size_t)(row + 8) * SEQ + col] = make_float2(c2, c3);
                }
            }
        }
    }
}

__global__ void __launch_bounds__(256, 2)
proj_qkv_kernel(const float* __restrict__ q, const float* __restrict__ k,
                const float* __restrict__ v,
                const float* __restrict__ Wq, const float* __restrict__ bq,
                const float* __restrict__ Wk, const float* __restrict__ bk,
                const float* __restrict__ Wv, const float* __restrict__ bv) {
    const int b = blockIdx.z & 3;
    const int which = blockIdx.z >> 2;   // 0:q 1:k 2:v
    const size_t off = (size_t)b * DMODEL * SEQ;
    if (which == 0)
        proj16_tile<0, 1, __half>(q + off, Wq, bq,
                                  g_qh + (size_t)b * NHEAD * SEQ * HDIM, QSCALE);
    else if (which == 1)
        proj16_tile<0, 1, __half>(k + off, Wk, bk,
                                  g_kh + (size_t)b * NHEAD * SEQ * HDIM, 1.f);
    else
        proj16_tile<0, 0, __half>(v + off, Wv, bv, g_vh + off, 1.f);
}

__global__ void __launch_bounds__(256, 2)
proj_out_kernel(const float* __restrict__ Wm, const float* __restrict__ bm,
                float* __restrict__ out) {
    const int b = blockIdx.z;
    const size_t off = (size_t)b * DMODEL * SEQ;
    proj16_tile<1, 0, float>(g_x + off, Wm, bm, out + off, 1.f);
}

// ---------------------------------------------------------------------------
__global__ void __launch_bounds__(256)
flags_kernel(const int* __restrict__ M) {
    const int row = blockIdx.x * 8 + (threadIdx.x >> 5);
    const int mt  = threadIdx.x & 31;
    const int4* p = (const int4*)(M + (size_t)row * SEQ + mt * 64);
    int ok = 1;
#pragma unroll
    for (int i = 0; i < 16; i++) {
        int4 v = p[i];
        ok &= (v.x == 1) & (v.y == 1) & (v.z == 1) & (v.w == 1);
    }
    unsigned bits = __ballot_sync(0xffffffffu, ok);
    if (mt == 0) g_flagbits[row] = bits;
}

// ---------------------------------------------------------------------------
// Flash attention: fp16 HMMA, ldmatrix frags, 3-stage cp.async K/V pipeline,
// one __syncthreads per tile. Row-sums l accumulated on the fma pipe (HADD2
// chains of the fp16 p values + fp32 cross-tile partials; quad shuffles once
// at the end) — no tensor-pipe work for l.
// smem: Qs[128*AS] | Ks[3][64*AS] | Vs[3][64*AS]
// ---------------------------------------------------------------------------
#define AS 72
#define Q_OFF 0
#define K_OFF (128 * AS)
#define KSTG  (64 * AS)
#define V_OFF (K_OFF + 3 * KSTG)
#define VSTG  (64 * AS)
#define SH_HALVES (V_OFF + 3 * VSTG)

__device__ __forceinline__ void attn_load_kv(unsigned sb, const __half* Kg,
                                             const __half* Vg, int h, int st,
                                             int m0, int tid) {
#pragma unroll
    for (int r = 0; r < 2; r++) {
        const int idx = tid + 256 * r;
        const int m = idx >> 3, c = idx & 7;
        cp16(sb + (K_OFF + st * KSTG + m * AS + c * 8) * 2,
             Kg + (size_t)(m0 + m) * HDIM + c * 8);
    }
#pragma unroll
    for (int r = 0; r < 2; r++) {
        const int idx = tid + 256 * r;
        const int d = idx >> 3, c = idx & 7;
        cp16(sb + (V_OFF + st * VSTG + d * AS + c * 8) * 2,
             Vg + (size_t)(d * 8 + h) * SEQ + m0 + c * 8);
    }
}

__global__ void __launch_bounds__(256, 2)
attn_kernel(const int* __restrict__ Mmask) {
    extern __shared__ __align__(16) __half sh[];

    const int tid  = threadIdx.x;
    const int wid  = tid >> 5;
    const int lane = tid & 31;
    const int g = lane >> 2;
    const int t = lane & 3;
    const int n0 = blockIdx.x * 128;
    const int b = blockIdx.y >> 3;
    const int h = blockIdx.y & 7;
    const int bh = b * NHEAD + h;

    const __half* Qg = g_qh + (size_t)bh * SEQ * HDIM;
    const __half* Kg = g_kh + (size_t)bh * SEQ * HDIM;
    const __half* Vg = g_vh + (size_t)b * DMODEL * SEQ;
    const unsigned sb = (unsigned)__cvta_generic_to_shared(sh);

    // ldmatrix per-lane base offset within a K/V stage
    const unsigned kbl = (unsigned)((lane & 7) * AS +
                                    ((lane >> 3) & 1) * 8 + (lane >> 4) * 16) * 2;

    // prologue: Q + tile0 (group 0), tile1 (group 1), tile2 (group 2)
#pragma unroll
    for (int r = 0; r < 4; r++) {
        const int idx = tid + 256 * r;
        const int n = idx >> 3, c = idx & 7;
        cp16(sb + (Q_OFF + n * AS + c * 8) * 2,
             Qg + (size_t)(n0 + n) * HDIM + c * 8);
    }
    attn_load_kv(sb, Kg, Vg, h, 0, 0, tid);
    cp_commit();
    attn_load_kv(sb, Kg, Vg, h, 1, 64, tid);
    cp_commit();
    attn_load_kv(sb, Kg, Vg, h, 2, 128, tid);
    cp_commit();

    cp_wait<2>();          // Q + tile0 resident
    __syncthreads();

    unsigned qA[4][4];
    const int row_s = 16 * wid + g;
#pragma unroll
    for (int ks = 0; ks < 4; ks++) {
        qA[ks][0] = *(const unsigned*)&sh[Q_OFF + row_s * AS + 16 * ks + 2 * t];
        qA[ks][1] = *(const unsigned*)&sh[Q_OFF + (row_s + 8) * AS + 16 * ks + 2 * t];
        qA[ks][2] = *(const unsigned*)&sh[Q_OFF + row_s * AS + 16 * ks + 2 * t + 8];
        qA[ks][3] = *(const unsigned*)&sh[Q_OFF + (row_s + 8) * AS + 16 * ks + 2 * t + 8];
    }

    const int row0 = n0 + 16 * wid + g;
    const unsigned fb0 = g_flagbits[(size_t)b * SEQ + row0];
    const unsigned fb1 = g_flagbits[(size_t)b * SEQ + row0 + 8];

    float o[8][4];
    float lp0 = 0.f, lp1 = 0.f;      // per-thread partial row sums
#pragma unroll
    for (int db = 0; db < 8; db++)
#pragma unroll
        for (int i = 0; i < 4; i++) o[db][i] = 0.f;

    int st = 0;
    for (int mt = 0; mt < 32; mt++) {
        const int m0 = mt * 64;
        const unsigned kaddr = sb + (unsigned)(K_OFF + st * KSTG) * 2 + kbl;
        const unsigned vaddr = sb + (unsigned)(V_OFF + st * VSTG) * 2 + kbl;

        cp_wait<1>();       // tile mt's group provably complete
        __syncthreads();    // data visible; all warps past iter mt-1

        // refill tile mt+2 into the stage consumed at iter mt-1
        if (mt >= 1 && mt + 2 < 32)
            attn_load_kv(sb, Kg, Vg, h, (mt + 2) % 3, (mt + 2) * 64, tid);
        cp_commit();        // uniform: one commit per iteration

        // ---- S = Q K^T (already exp2-scaled via Q prescale) ----
        float s_[8][4];
#pragma unroll
        for (int nb = 0; nb < 8; nb++) {
#pragma unroll
            for (int i = 0; i < 4; i++) s_[nb][i] = 0.f;
            unsigned kf[8];
            const unsigned ka = kaddr + (unsigned)(8 * nb * AS) * 2;
            ldsm_x4(kf, ka);
            ldsm_x4(kf + 4, ka + 64);
            mma16816(s_[nb], qA[0], kf[0], kf[1]);
            mma16816(s_[nb], qA[1], kf[2], kf[3]);
            mma16816(s_[nb], qA[2], kf[4], kf[5]);
            mma16816(s_[nb], qA[3], kf[6], kf[7]);
        }

        // ---- mask (rare path) ----
        if (!(((fb0 >> mt) & 1u) & ((fb1 >> mt) & 1u))) {
#pragma unroll
            for (int nb = 0; nb < 8; nb++) {
                int2 mv0 = *(const int2*)&Mmask[((size_t)b * SEQ + row0) * SEQ + m0 + 8 * nb + 2 * t];
                int2 mv1 = *(const int2*)&Mmask[((size_t)b * SEQ + row0 + 8) * SEQ + m0 + 8 * nb + 2 * t];
                if (mv0.x != 1) s_[nb][0] = -FLT_MAX;
                if (mv0.y != 1) s_[nb][1] = -FLT_MAX;
                if (mv1.x != 1) s_[nb][2] = -FLT_MAX;
                if (mv1.y != 1) s_[nb][3] = -FLT_MAX;
            }
        }

        // ---- p = 2^s, packed fp16 ----
        unsigned pa0[8], pa1[8];
#pragma unroll
        for (int nb = 0; nb < 8; nb++) {
            pa0[nb] = ex2_h2(pack_h2(s_[nb][0], s_[nb][1]));
            pa1[nb] = ex2_h2(pack_h2(s_[nb][2], s_[nb][3]));
        }

        // ---- l partials on the fma pipe (HADD2 chain + fp32 accumulate) ----
        {
            __half2 s0 = *(__half2*)&pa0[0];
            __half2 s1 = *(__half2*)&pa1[0];
#pragma unroll
            for (int nb = 1; nb < 8; nb++) {
                s0 = __hadd2(s0, *(__half2*)&pa0[nb]);
                s1 = __hadd2(s1, *(__half2*)&pa1[nb]);
            }
            float2 f0 = __half22float2(s0);
            float2 f1 = __half22float2(s1);
            lp0 += f0.x + f0.y;
            lp1 += f1.x + f1.y;
        }

        // ---- O += P V ----
#pragma unroll
        for (int db = 0; db < 8; db++) {
            unsigned vf[8];
            const unsigned va = vaddr + (unsigned)(8 * db * AS) * 2;
            ldsm_x4(vf, va);
            ldsm_x4(vf + 4, va + 64);
            { unsigned a[4] = {pa0[0], pa1[0], pa0[1], pa1[1]}; mma16816(o[db], a, vf[0], vf[1]); }
            { unsigned a[4] = {pa0[2], pa1[2], pa0[3], pa1[3]}; mma16816(o[db], a, vf[2], vf[3]); }
            { unsigned a[4] = {pa0[4], pa1[4], pa0[5], pa1[5]}; mma16816(o[db], a, vf[4], vf[5]); }
            { unsigned a[4] = {pa0[6], pa1[6], pa0[7], pa1[7]}; mma16816(o[db], a, vf[6], vf[7]); }
        }

        st = (st == 2) ? 0 : st + 1;
    }

    // ---- finish l: reduce across the quad (cols split over t) ----
    lp0 += __shfl_xor_sync(0xffffffffu, lp0, 1);
    lp0 += __shfl_xor_sync(0xffffffffu, lp0, 2);
    lp1 += __shfl_xor_sync(0xffffffffu, lp1, 1);
    lp1 += __shfl_xor_sync(0xffffffffu, lp1, 2);
    const float inv0 = 1.f / lp0;
    const float inv1 = 1.f / lp1;

    float* Xb = g_x + (size_t)b * DMODEL * SEQ;
#pragma unroll
    for (int db = 0; db < 8; db++) {
        const int d0 = 8 * db + 2 * t;
        Xb[(size_t)(d0 * 8 + h) * SEQ + row0]           = o[db][0] * inv0;
        Xb[(size_t)((d0 + 1) * 8 + h) * SEQ + row0]     = o[db][1] * inv0;
        Xb[(size_t)(d0 * 8 + h) * SEQ + row0 + 8]       = o[db][2] * inv1;
        Xb[(size_t)((d0 + 1) * 8 + h) * SEQ + row0 + 8] = o[db][3] * inv1;
    }
}

// ---------------------------------------------------------------------------
extern "C" void kernel_launch(void* const* d_in, const int* in_sizes, int n_in,
                              void* d_out, int out_size) {
    const float* q  = (const float*)d_in[0];
    const float* k  = (const float*)d_in[1];
    const float* v  = (const float*)d_in[2];
    const int*   Mm = (const int*)  d_in[3];
    const float* Wq = (const float*)d_in[4];
    const float* bq = (const float*)d_in[5];
    const float* Wk = (const float*)d_in[6];
    const float* bk = (const float*)d_in[7];
    const float* Wv = (const float*)d_in[8];
    const float* bv = (const float*)d_in[9];
    const float* Wm = (const float*)d_in[10];
    const float* bm = (const float*)d_in[11];
    float* out = (float*)d_out;

    flags_kernel<<<BATCH * SEQ / 8, 256>>>(Mm);

    dim3 gqkv(SEQ / 128, DMODEL / 128, 3 * BATCH);
    proj_qkv_kernel<<<gqkv, 256>>>(q, k, v, Wq, bq, Wk, bk, Wv, bv);

    const int smem_attn = SH_HALVES * 2;
    cudaFuncSetAttribute(attn_kernel, cudaFuncAttributeMaxDynamicSharedMemorySize, smem_attn);
    dim3 gattn(SEQ / 128, BATCH * NHEAD);
    attn_kernel<<<gattn, 256, smem_attn>>>(Mm);

    dim3 gout(SEQ / 128, DMODEL / 128, BATCH);
    proj_out_kernel<<<gout, 256>>>(Wm, bm, out);
}